// round 4
// baseline (speedup 1.0000x reference)
#include <cuda_runtime.h>
#include <cuda_fp16.h>
#include <cstdint>

// ----------------------------------------------------------------------------
// LatentReasoningModule, sm_100 legacy tensor-core path.
//   fp16 mma.m16n8k16 (fp32 accum), ldmatrix, 3-stage cp.async.
//   encode: H(2048)->2L(1024) relu ->L(512)
//   8x GRU(512): ONE fused GEMM+gate kernel per step (BN=192 gate-grouped
//                weight layout; epilogue computes sigmoid/tanh, writes latent)
//   decode: L->2L relu ->H
// ----------------------------------------------------------------------------

#define MROWS 8192
#define THREADS 256
#define SROW 144                    // bytes per smem row: 64 halves + 8 pad

// ---- main GEMM tile (encode/decode) ----
#define BM 128
#define BN 128
#define BK 64
#define AB_BYTES   (BM * SROW)          // 18432
#define STG_BYTES  (2 * AB_BYTES)       // 36864
#define SMEM_MAIN  (3 * STG_BYTES)      // 110592

// ---- GRU GEMM tile ----
#define GBM 128
#define GBN 192
#define GSTG_BYTES ((GBM + GBN) * SROW) // 46080
#define SMEM_GRU   (3 * GSTG_BYTES)     // 138240  (epilogue staging 128*196*4 = 100352 fits)
#define EPS 196                          // epilogue staging stride (floats)

// ---------------- scratch (device globals) ------------------------------------
__device__ __half g_xh[(size_t)MROWS * 2048];
__device__ __half g_h1h[(size_t)MROWS * 1024];
__device__ __half g_lath[2][(size_t)MROWS * 512];
__device__ float  g_latf[2][(size_t)MROWS * 512];
// enc/dec weights fp16, concatenated
#define OFF_ENC1  0
#define OFF_ENC2  2097152
#define OFF_DEC1  2621440
#define OFF_DEC2  3145728
__device__ __half g_wh[5242880];
__device__ __half g_wgru[3072 * 512];   // gate-grouped GRU weights
__device__ float  g_bgru[3072];         // gate-grouped GRU bias

// ---------------- helpers -----------------------------------------------------
__device__ __forceinline__ uint32_t smem_u32(const void* p) {
    uint32_t a;
    asm("{ .reg .u64 t; cvta.to.shared.u64 t, %1; cvt.u32.u64 %0, t; }"
        : "=r"(a) : "l"(p));
    return a;
}
__device__ __forceinline__ void cp16(uint32_t dst, const void* src) {
    asm volatile("cp.async.cg.shared.global [%0], [%1], 16;"
                 :: "r"(dst), "l"(src));
}
__device__ __forceinline__ void cp_commit() {
    asm volatile("cp.async.commit_group;" ::: "memory");
}
template <int N>
__device__ __forceinline__ void cp_wait() {
    asm volatile("cp.async.wait_group %0;" :: "n"(N) : "memory");
}
__device__ __forceinline__ void ldsm4(uint32_t* r, uint32_t addr) {
    asm volatile("ldmatrix.sync.aligned.m8n8.x4.shared.b16 {%0,%1,%2,%3}, [%4];"
                 : "=r"(r[0]), "=r"(r[1]), "=r"(r[2]), "=r"(r[3]) : "r"(addr));
}
__device__ __forceinline__ void mma16(float* c, const uint32_t* a, const uint32_t* b) {
    asm volatile(
        "mma.sync.aligned.m16n8k16.row.col.f32.f16.f16.f32 "
        "{%0,%1,%2,%3},{%4,%5,%6,%7},{%8,%9},{%0,%1,%2,%3};"
        : "+f"(c[0]), "+f"(c[1]), "+f"(c[2]), "+f"(c[3])
        : "r"(a[0]), "r"(a[1]), "r"(a[2]), "r"(a[3]), "r"(b[0]), "r"(b[1]));
}
__device__ __forceinline__ float sigmf(float x) {
    return 1.f / (1.f + __expf(-x));
}

// ---------------- main fp16 GEMM (encode/decode) ------------------------------
// C[M,N] = op(A[M,K] @ B[N,K]^T + bias). M%128==0, N%128==0, K%192... K%64==0.
__global__ __launch_bounds__(THREADS, 2) void gemm_f16(
    const __half* __restrict__ A, int lda,
    const __half* __restrict__ B, int ldb,
    const float* __restrict__ bias,
    float* __restrict__ Cf, __half* __restrict__ Ch, int ldc,
    int K, int do_relu)
{
    extern __shared__ __align__(16) char sm[];
    const uint32_t sbase = smem_u32(sm);

    const int tid  = threadIdx.x;
    const int warp = tid >> 5;
    const int lane = tid & 31;
    const int bm = blockIdx.y * BM;
    const int bn = blockIdx.x * BN;
    const int wm = (warp & 3) * 32;
    const int wn = (warp >> 2) * 64;
    const int grp = lane >> 2;
    const int qid = lane & 3;
    const int arow = ((lane >> 3) & 1) * 8 + (lane & 7);
    const int acol = ((lane >> 4) & 1) * 8;
    const int brow = ((lane >> 4) & 1) * 8 + (lane & 7);
    const int bcol = ((lane >> 3) & 1) * 8;

    float acc[2][8][4];
#pragma unroll
    for (int i = 0; i < 2; i++)
#pragma unroll
        for (int j = 0; j < 8; j++)
#pragma unroll
            for (int k = 0; k < 4; k++) acc[i][j][k] = 0.f;

    const int niter = K / BK;

    auto load_tile = [&](int it) {
        const int k0 = it * BK;
        const uint32_t sa = sbase + (uint32_t)(it % 3) * STG_BYTES;
        const uint32_t sb = sa + AB_BYTES;
#pragma unroll
        for (int t = tid; t < 1024; t += THREADS) {
            int r = t >> 3, c = t & 7;
            cp16(sa + r * SROW + c * 16, A + (size_t)(bm + r) * lda + k0 + c * 8);
        }
#pragma unroll
        for (int t = tid; t < 1024; t += THREADS) {
            int r = t >> 3, c = t & 7;
            cp16(sb + r * SROW + c * 16, B + (size_t)(bn + r) * ldb + k0 + c * 8);
        }
        cp_commit();
    };

    load_tile(0);
    load_tile(1);

    for (int it = 0; it < niter; it++) {
        if (it + 2 < niter) { load_tile(it + 2); cp_wait<2>(); }
        else if (it + 1 < niter) cp_wait<1>();
        else cp_wait<0>();
        __syncthreads();

        const uint32_t sa = sbase + (uint32_t)(it % 3) * STG_BYTES;
        const uint32_t sb = sa + AB_BYTES;

#pragma unroll
        for (int kk = 0; kk < BK; kk += 16) {
            uint32_t af[2][4], bf[8][2];
#pragma unroll
            for (int mt = 0; mt < 2; mt++)
                ldsm4(af[mt], sa + (wm + mt * 16 + arow) * SROW + (kk + acol) * 2);
#pragma unroll
            for (int np = 0; np < 4; np++) {
                uint32_t r[4];
                ldsm4(r, sb + (wn + np * 16 + brow) * SROW + (kk + bcol) * 2);
                bf[2 * np][0] = r[0]; bf[2 * np][1] = r[1];
                bf[2 * np + 1][0] = r[2]; bf[2 * np + 1][1] = r[3];
            }
#pragma unroll
            for (int mt = 0; mt < 2; mt++)
#pragma unroll
                for (int nt = 0; nt < 8; nt++)
                    mma16(acc[mt][nt], af[mt], bf[nt]);
        }
        __syncthreads();
    }

#pragma unroll
    for (int mt = 0; mt < 2; mt++) {
#pragma unroll
        for (int nt = 0; nt < 8; nt++) {
            int colN = bn + wn + nt * 8 + qid * 2;
            int row  = bm + wm + mt * 16 + grp;
            float2 bv = *(const float2*)(bias + colN);
            float2 v0, v1;
            v0.x = acc[mt][nt][0] + bv.x; v0.y = acc[mt][nt][1] + bv.y;
            v1.x = acc[mt][nt][2] + bv.x; v1.y = acc[mt][nt][3] + bv.y;
            if (do_relu) {
                v0.x = fmaxf(v0.x, 0.f); v0.y = fmaxf(v0.y, 0.f);
                v1.x = fmaxf(v1.x, 0.f); v1.y = fmaxf(v1.y, 0.f);
            }
            if (Cf) {
                *(float2*)(Cf + (size_t)row * ldc + colN)       = v0;
                *(float2*)(Cf + (size_t)(row + 8) * ldc + colN) = v1;
            }
            if (Ch) {
                *(__half2*)(Ch + (size_t)row * ldc + colN)       = __floats2half2_rn(v0.x, v0.y);
                *(__half2*)(Ch + (size_t)(row + 8) * ldc + colN) = __floats2half2_rn(v1.x, v1.y);
            }
        }
    }
}

// ---------------- fused GRU step: GEMM (N=192 gate-grouped) + gates ------------
// A = lath_in [8192x512] fp16. Weights wg [3072x512] fp16 grouped so that
// output block bn..bn+191 = (i_r|i_z|i_n|h_r|h_z|h_n) x 32 latent dims.
// Epilogue: stage acc to smem, compute GRU update, write latf/lath/traj.
__global__ __launch_bounds__(THREADS) void gemm_gru(
    const __half* __restrict__ A,
    const float* __restrict__ latf_in,
    float* __restrict__ latf_out, __half* __restrict__ lath_out,
    float* __restrict__ traj, int step)
{
    extern __shared__ __align__(16) char sm[];
    const uint32_t sbase = smem_u32(sm);

    const int tid  = threadIdx.x;
    const int warp = tid >> 5;
    const int lane = tid & 31;
    const int bm = blockIdx.y * GBM;
    const int blk = blockIdx.x;          // latent 32-dim block
    const int wm = (warp & 3) * 32;
    const int wn = (warp >> 2) * 96;
    const int grp = lane >> 2;
    const int qid = lane & 3;
    const int arow = ((lane >> 3) & 1) * 8 + (lane & 7);
    const int acol = ((lane >> 4) & 1) * 8;
    const int brow = ((lane >> 4) & 1) * 8 + (lane & 7);
    const int bcol = ((lane >> 3) & 1) * 8;

    const __half* Bw = g_wgru + (size_t)blk * 192 * 512;

    float acc[2][12][4];
#pragma unroll
    for (int i = 0; i < 2; i++)
#pragma unroll
        for (int j = 0; j < 12; j++)
#pragma unroll
            for (int k = 0; k < 4; k++) acc[i][j][k] = 0.f;

    const int niter = 512 / BK;          // 8

    auto load_tile = [&](int it) {
        const int k0 = it * BK;
        const uint32_t sa = sbase + (uint32_t)(it % 3) * GSTG_BYTES;
        const uint32_t sb = sa + GBM * SROW;
#pragma unroll
        for (int t = tid; t < 1024; t += THREADS) {       // A: 128 rows x 8
            int r = t >> 3, c = t & 7;
            cp16(sa + r * SROW + c * 16, A + (size_t)(bm + r) * 512 + k0 + c * 8);
        }
#pragma unroll
        for (int t = tid; t < 1536; t += THREADS) {       // B: 192 rows x 8
            int r = t >> 3, c = t & 7;
            cp16(sb + r * SROW + c * 16, Bw + (size_t)r * 512 + k0 + c * 8);
        }
        cp_commit();
    };

    load_tile(0);
    load_tile(1);

    for (int it = 0; it < niter; it++) {
        if (it + 2 < niter) { load_tile(it + 2); cp_wait<2>(); }
        else if (it + 1 < niter) cp_wait<1>();
        else cp_wait<0>();
        __syncthreads();

        const uint32_t sa = sbase + (uint32_t)(it % 3) * GSTG_BYTES;
        const uint32_t sb = sa + GBM * SROW;

#pragma unroll
        for (int kk = 0; kk < BK; kk += 16) {
            uint32_t af[2][4], bf[12][2];
#pragma unroll
            for (int mt = 0; mt < 2; mt++)
                ldsm4(af[mt], sa + (wm + mt * 16 + arow) * SROW + (kk + acol) * 2);
#pragma unroll
            for (int np = 0; np < 6; np++) {
                uint32_t r[4];
                ldsm4(r, sb + (wn + np * 16 + brow) * SROW + (kk + bcol) * 2);
                bf[2 * np][0] = r[0]; bf[2 * np][1] = r[1];
                bf[2 * np + 1][0] = r[2]; bf[2 * np + 1][1] = r[3];
            }
#pragma unroll
            for (int mt = 0; mt < 2; mt++)
#pragma unroll
                for (int nt = 0; nt < 12; nt++)
                    mma16(acc[mt][nt], af[mt], bf[nt]);
        }
        __syncthreads();
    }

    // ---- epilogue: stage acc tile [128 x 192] fp32 into smem ----
    float* st = (float*)sm;
#pragma unroll
    for (int mt = 0; mt < 2; mt++) {
#pragma unroll
        for (int nt = 0; nt < 12; nt++) {
            int r0 = wm + mt * 16 + grp;
            int cc = wn + nt * 8 + qid * 2;
            *(float2*)&st[r0 * EPS + cc]       = make_float2(acc[mt][nt][0], acc[mt][nt][1]);
            *(float2*)&st[(r0 + 8) * EPS + cc] = make_float2(acc[mt][nt][2], acc[mt][nt][3]);
        }
    }
    __syncthreads();

    // ---- GRU gate math: each thread handles d = tid%32, rows tid/32 + 8j ----
    const int d = tid & 31;
    const int c = blk * 32 + d;
    const float* bg = g_bgru + blk * 192;
    const float b_ir = bg[d],       b_iz = bg[32 + d],  b_in = bg[64 + d];
    const float b_hr = bg[96 + d],  b_hz = bg[128 + d], b_hn = bg[160 + d];

#pragma unroll
    for (int j = 0; j < 16; j++) {
        int r = (tid >> 5) + j * 8;
        int row = bm + r;
        const float* sr = st + r * EPS;
        float i_r = sr[d]       + b_ir;
        float i_z = sr[32 + d]  + b_iz;
        float i_n = sr[64 + d]  + b_in;
        float h_r = sr[96 + d]  + b_hr;
        float h_z = sr[128 + d] + b_hz;
        float h_n = sr[160 + d] + b_hn;
        float h = latf_in[(size_t)row * 512 + c];
        float rg = sigmf(i_r + h_r);
        float z  = sigmf(i_z + h_z);
        float n  = tanhf(i_n + rg * h_n);
        float out = (1.f - z) * n + z * h;
        latf_out[(size_t)row * 512 + c] = out;
        lath_out[(size_t)row * 512 + c] = __float2half_rn(out);
        traj[(size_t)row * 4096 + step * 512 + c] = out;
    }
}

// ---------------- prep kernels -------------------------------------------------
__global__ __launch_bounds__(256) void f2h(const float4* __restrict__ in,
                                           __half2* __restrict__ out, int n4)
{
    int i = blockIdx.x * blockDim.x + threadIdx.x;
    if (i >= n4) return;
    float4 v = in[i];
    out[2 * i]     = __floats2half2_rn(v.x, v.y);
    out[2 * i + 1] = __floats2half2_rn(v.z, v.w);
}

// gate-grouped GRU weight reorder: out row o = blk*192 + g*32 + d  ->
//   g<3: w_ih[g*512 + blk*32+d], else w_hh[(g-3)*512 + blk*32+d]
__global__ __launch_bounds__(256) void reorder_w(
    const float* __restrict__ w_ih, const float* __restrict__ w_hh,
    __half* __restrict__ wg)
{
    int idx = blockIdx.x * blockDim.x + threadIdx.x;   // 3072*128
    if (idx >= 3072 * 128) return;
    int o = idx >> 7, q = idx & 127;
    int blk = o / 192, rem = o % 192, g = rem >> 5, dd = rem & 31;
    int c = blk * 32 + dd;
    const float* src = (g < 3) ? (w_ih + (size_t)(g * 512 + c) * 512)
                               : (w_hh + (size_t)((g - 3) * 512 + c) * 512);
    float4 v = ((const float4*)src)[q];
    __half2* dst = (__half2*)(wg + (size_t)o * 512 + q * 4);
    dst[0] = __floats2half2_rn(v.x, v.y);
    dst[1] = __floats2half2_rn(v.z, v.w);
}
__global__ __launch_bounds__(256) void reorder_b(
    const float* __restrict__ b_ih, const float* __restrict__ b_hh,
    float* __restrict__ bg)
{
    int o = blockIdx.x * blockDim.x + threadIdx.x;
    if (o >= 3072) return;
    int blk = o / 192, rem = o % 192, g = rem >> 5, dd = rem & 31;
    int c = blk * 32 + dd;
    bg[o] = (g < 3) ? b_ih[g * 512 + c] : b_hh[(g - 3) * 512 + c];
}

// ---------------- launch -------------------------------------------------------
extern "C" void kernel_launch(void* const* d_in, const int* in_sizes, int n_in,
                              void* d_out, int out_size)
{
    const int bse = (n_in >= 14) ? 2 : 1;
    const float* x      = (const float*)d_in[0];
    const float* W_enc1 = (const float*)d_in[bse + 0];
    const float* b_enc1 = (const float*)d_in[bse + 1];
    const float* W_enc2 = (const float*)d_in[bse + 2];
    const float* b_enc2 = (const float*)d_in[bse + 3];
    const float* W_dec1 = (const float*)d_in[bse + 4];
    const float* b_dec1 = (const float*)d_in[bse + 5];
    const float* W_dec2 = (const float*)d_in[bse + 6];
    const float* b_dec2 = (const float*)d_in[bse + 7];
    const float* w_ih   = (const float*)d_in[bse + 8];
    const float* w_hh   = (const float*)d_in[bse + 9];
    const float* b_ih   = (const float*)d_in[bse + 10];
    const float* b_hh   = (const float*)d_in[bse + 11];

    float* decoded = (float*)d_out;
    float* traj    = decoded + (size_t)MROWS * 2048;

    __half *xh, *h1h, *wh, *wg;
    __half *lath[2];
    float *latf[2], *bg;
    cudaGetSymbolAddress((void**)&xh,  g_xh);
    cudaGetSymbolAddress((void**)&h1h, g_h1h);
    cudaGetSymbolAddress((void**)&wh,  g_wh);
    cudaGetSymbolAddress((void**)&wg,  g_wgru);
    cudaGetSymbolAddress((void**)&bg,  g_bgru);
    {   __half* p; cudaGetSymbolAddress((void**)&p, g_lath);
        lath[0] = p; lath[1] = p + (size_t)MROWS * 512; }
    {   float* p; cudaGetSymbolAddress((void**)&p, g_latf);
        latf[0] = p; latf[1] = p + (size_t)MROWS * 512; }

    cudaFuncSetAttribute(gemm_f16, cudaFuncAttributeMaxDynamicSharedMemorySize, SMEM_MAIN);
    cudaFuncSetAttribute(gemm_gru, cudaFuncAttributeMaxDynamicSharedMemorySize, SMEM_GRU);

    auto cvt = [&](const float* src, __half* dst, int n) {
        f2h<<<(n / 4 + 255) / 256, 256>>>((const float4*)src, (__half2*)dst, n / 4);
    };
    cvt(x,      xh,            MROWS * 2048);
    cvt(W_enc1, wh + OFF_ENC1, 1024 * 2048);
    cvt(W_enc2, wh + OFF_ENC2, 512 * 1024);
    cvt(W_dec1, wh + OFF_DEC1, 1024 * 512);
    cvt(W_dec2, wh + OFF_DEC2, 2048 * 1024);
    reorder_w<<<(3072 * 128 + 255) / 256, 256>>>(w_ih, w_hh, wg);
    reorder_b<<<(3072 + 255) / 256, 256>>>(b_ih, b_hh, bg);

    const dim3 blk(THREADS);
    const int gy = MROWS / BM;  // 64

    // encode
    gemm_f16<<<dim3(1024 / BN, gy), blk, SMEM_MAIN>>>(
        xh, 2048, wh + OFF_ENC1, 2048, b_enc1, nullptr, h1h, 1024, 2048, 1);
    gemm_f16<<<dim3(512 / BN, gy), blk, SMEM_MAIN>>>(
        h1h, 1024, wh + OFF_ENC2, 1024, b_enc2, latf[0], lath[0], 512, 1024, 0);

    // 8 fused GRU steps (ping-pong latent buffers)
    for (int step = 0; step < 8; step++) {
        int s = step & 1, t = s ^ 1;
        gemm_gru<<<dim3(16, MROWS / GBM), blk, SMEM_GRU>>>(
            lath[s], latf[s], latf[t], lath[t], traj, step);
    }

    // decode (final latent is in buffer 0 after 8 steps)
    gemm_f16<<<dim3(1024 / BN, gy), blk, SMEM_MAIN>>>(
        lath[0], 512, wh + OFF_DEC1, 512, b_dec1, nullptr, h1h, 1024, 512, 1);
    gemm_f16<<<dim3(2048 / BN, gy), blk, SMEM_MAIN>>>(
        h1h, 1024, wh + OFF_DEC2, 1024, b_dec2, decoded, nullptr, 2048, 1024, 0);
}

// round 5
// speedup vs baseline: 1.2591x; 1.2591x over previous
#include <cuda_runtime.h>
#include <cuda_fp16.h>
#include <cstdint>

// ----------------------------------------------------------------------------
// LatentReasoningModule, sm_100 legacy tensor-core path.
//   fp16 mma.m16n8k16 (fp32 accum), ldmatrix, cp.async.
//   encode: H(2048)->2L(1024) relu ->L(512)
//   8x GRU(512): fused GEMM+gate kernel, 8-dim gate-grouped weights so the
//                gate math is register-local per thread (no smem staging).
//   decode: L->2L relu ->H
// ----------------------------------------------------------------------------

#define MROWS 8192
#define THREADS 256
#define SROW 144                    // bytes per smem row: 64 halves + 8 pad

// ---- main GEMM tile (encode/decode): R3 config, 2-stage ----
#define BM 128
#define BN 128
#define BK 64
#define AB_BYTES   (BM * SROW)          // 18432
#define STG_BYTES  (2 * AB_BYTES)       // 36864
#define SMEM_MAIN  (2 * STG_BYTES)      // 73728

// ---- GRU GEMM tile: BM=128, BN=96 (2 x 48-col gate groups), 2-stage ----
#define GBN 96
#define GSTG_BYTES ((BM + GBN) * SROW)  // 32256
#define SMEM_GRU   (2 * GSTG_BYTES)     // 64512

// ---------------- scratch (device globals) ------------------------------------
__device__ __half g_xh[(size_t)MROWS * 2048];
__device__ __half g_h1h[(size_t)MROWS * 1024];
__device__ __half g_lath[2][(size_t)MROWS * 512];
__device__ float  g_latf[2][(size_t)MROWS * 512];
#define OFF_ENC1  0
#define OFF_ENC2  2097152
#define OFF_DEC1  2621440
#define OFF_DEC2  3145728
__device__ __half g_wh[5242880];
__device__ __half g_wgru[3072 * 512];   // gate-grouped GRU weights (8-dim groups)

// ---------------- helpers -----------------------------------------------------
__device__ __forceinline__ uint32_t smem_u32(const void* p) {
    uint32_t a;
    asm("{ .reg .u64 t; cvta.to.shared.u64 t, %1; cvt.u32.u64 %0, t; }"
        : "=r"(a) : "l"(p));
    return a;
}
__device__ __forceinline__ void cp16(uint32_t dst, const void* src) {
    asm volatile("cp.async.cg.shared.global [%0], [%1], 16;"
                 :: "r"(dst), "l"(src));
}
__device__ __forceinline__ void cp_commit() {
    asm volatile("cp.async.commit_group;" ::: "memory");
}
template <int N>
__device__ __forceinline__ void cp_wait() {
    asm volatile("cp.async.wait_group %0;" :: "n"(N) : "memory");
}
__device__ __forceinline__ void ldsm4(uint32_t* r, uint32_t addr) {
    asm volatile("ldmatrix.sync.aligned.m8n8.x4.shared.b16 {%0,%1,%2,%3}, [%4];"
                 : "=r"(r[0]), "=r"(r[1]), "=r"(r[2]), "=r"(r[3]) : "r"(addr));
}
__device__ __forceinline__ void mma16(float* c, const uint32_t* a, const uint32_t* b) {
    asm volatile(
        "mma.sync.aligned.m16n8k16.row.col.f32.f16.f16.f32 "
        "{%0,%1,%2,%3},{%4,%5,%6,%7},{%8,%9},{%0,%1,%2,%3};"
        : "+f"(c[0]), "+f"(c[1]), "+f"(c[2]), "+f"(c[3])
        : "r"(a[0]), "r"(a[1]), "r"(a[2]), "r"(a[3]), "r"(b[0]), "r"(b[1]));
}
__device__ __forceinline__ float sigmf(float x) {
    return 1.f / (1.f + __expf(-x));
}

// ---------------- main fp16 GEMM (encode/decode) — R3 config ------------------
__global__ __launch_bounds__(THREADS, 2) void gemm_f16(
    const __half* __restrict__ A, int lda,
    const __half* __restrict__ B, int ldb,
    const float* __restrict__ bias,
    float* __restrict__ Cf, __half* __restrict__ Ch, int ldc,
    int K, int do_relu)
{
    extern __shared__ __align__(16) char sm[];
    const uint32_t sbase = smem_u32(sm);

    const int tid  = threadIdx.x;
    const int warp = tid >> 5;
    const int lane = tid & 31;
    const int bm = blockIdx.y * BM;
    const int bn = blockIdx.x * BN;
    const int wm = (warp & 3) * 32;
    const int wn = (warp >> 2) * 64;
    const int grp = lane >> 2;
    const int qid = lane & 3;
    const int arow = ((lane >> 3) & 1) * 8 + (lane & 7);
    const int acol = ((lane >> 4) & 1) * 8;
    const int brow = ((lane >> 4) & 1) * 8 + (lane & 7);
    const int bcol = ((lane >> 3) & 1) * 8;

    float acc[2][8][4];
#pragma unroll
    for (int i = 0; i < 2; i++)
#pragma unroll
        for (int j = 0; j < 8; j++)
#pragma unroll
            for (int k = 0; k < 4; k++) acc[i][j][k] = 0.f;

    const int niter = K / BK;

    auto load_tile = [&](int it) {
        const int k0 = it * BK;
        const uint32_t sa = sbase + (uint32_t)(it & 1) * STG_BYTES;
        const uint32_t sb = sa + AB_BYTES;
#pragma unroll
        for (int t = tid; t < 1024; t += THREADS) {
            int r = t >> 3, c = t & 7;
            cp16(sa + r * SROW + c * 16, A + (size_t)(bm + r) * lda + k0 + c * 8);
        }
#pragma unroll
        for (int t = tid; t < 1024; t += THREADS) {
            int r = t >> 3, c = t & 7;
            cp16(sb + r * SROW + c * 16, B + (size_t)(bn + r) * ldb + k0 + c * 8);
        }
        cp_commit();
    };

    load_tile(0);

    for (int it = 0; it < niter; it++) {
        if (it + 1 < niter) {
            load_tile(it + 1);
            cp_wait<1>();
        } else {
            cp_wait<0>();
        }
        __syncthreads();

        const uint32_t sa = sbase + (uint32_t)(it & 1) * STG_BYTES;
        const uint32_t sb = sa + AB_BYTES;

#pragma unroll
        for (int kk = 0; kk < BK; kk += 16) {
            uint32_t af[2][4], bf[8][2];
#pragma unroll
            for (int mt = 0; mt < 2; mt++)
                ldsm4(af[mt], sa + (wm + mt * 16 + arow) * SROW + (kk + acol) * 2);
#pragma unroll
            for (int np = 0; np < 4; np++) {
                uint32_t r[4];
                ldsm4(r, sb + (wn + np * 16 + brow) * SROW + (kk + bcol) * 2);
                bf[2 * np][0] = r[0]; bf[2 * np][1] = r[1];
                bf[2 * np + 1][0] = r[2]; bf[2 * np + 1][1] = r[3];
            }
#pragma unroll
            for (int mt = 0; mt < 2; mt++)
#pragma unroll
                for (int nt = 0; nt < 8; nt++)
                    mma16(acc[mt][nt], af[mt], bf[nt]);
        }
        __syncthreads();
    }

#pragma unroll
    for (int mt = 0; mt < 2; mt++) {
#pragma unroll
        for (int nt = 0; nt < 8; nt++) {
            int colN = bn + wn + nt * 8 + qid * 2;
            int row  = bm + wm + mt * 16 + grp;
            float2 bv = *(const float2*)(bias + colN);
            float2 v0, v1;
            v0.x = acc[mt][nt][0] + bv.x; v0.y = acc[mt][nt][1] + bv.y;
            v1.x = acc[mt][nt][2] + bv.x; v1.y = acc[mt][nt][3] + bv.y;
            if (do_relu) {
                v0.x = fmaxf(v0.x, 0.f); v0.y = fmaxf(v0.y, 0.f);
                v1.x = fmaxf(v1.x, 0.f); v1.y = fmaxf(v1.y, 0.f);
            }
            if (Cf) {
                *(float2*)(Cf + (size_t)row * ldc + colN)       = v0;
                *(float2*)(Cf + (size_t)(row + 8) * ldc + colN) = v1;
            }
            if (Ch) {
                *(__half2*)(Ch + (size_t)row * ldc + colN)       = __floats2half2_rn(v0.x, v0.y);
                *(__half2*)(Ch + (size_t)(row + 8) * ldc + colN) = __floats2half2_rn(v1.x, v1.y);
            }
        }
    }
}

// ---------------- fused GRU step ----------------------------------------------
// A = lath_in [8192x512] fp16. g_wgru rows grouped per 8 latent dims:
//   row o: d48 = o/48, g = (o%48)/8, e = o%8;  latent dim c = d48*8 + e;
//   source = g<3 ? w_ih[g*512+c] : w_hh[(g-3)*512+c].
// CTA tile: 128 rows x 96 cols (= 2 x 48-groups = 16 latent dims, all 6 gates).
// Warp tile: 32 x 48 (one 48-group): acc[mt][g] holds gate g for the warp's
// 8 dims; each thread privately owns gates for dims qid*2, qid*2+1.
__global__ __launch_bounds__(THREADS, 2) void gemm_gru(
    const __half* __restrict__ A,
    const float* __restrict__ b_ih, const float* __restrict__ b_hh,
    const float* __restrict__ latf_in,
    float* __restrict__ latf_out, __half* __restrict__ lath_out,
    float* __restrict__ traj, int step)
{
    extern __shared__ __align__(16) char sm[];
    const uint32_t sbase = smem_u32(sm);

    const int tid  = threadIdx.x;
    const int warp = tid >> 5;
    const int lane = tid & 31;
    const int bm  = blockIdx.y * BM;
    const int blk = blockIdx.x;               // 16-dim block, 0..31
    const int wm = (warp & 3) * 32;
    const int wn = (warp >> 2) * 48;          // 0 or 48
    const int grp = lane >> 2;
    const int qid = lane & 3;
    const int arow = ((lane >> 3) & 1) * 8 + (lane & 7);
    const int acol = ((lane >> 4) & 1) * 8;
    const int brow = ((lane >> 4) & 1) * 8 + (lane & 7);
    const int bcol = ((lane >> 3) & 1) * 8;

    const __half* Bw = g_wgru + (size_t)blk * GBN * 512;

    float acc[2][6][4];
#pragma unroll
    for (int i = 0; i < 2; i++)
#pragma unroll
        for (int j = 0; j < 6; j++)
#pragma unroll
            for (int k = 0; k < 4; k++) acc[i][j][k] = 0.f;

    const int niter = 512 / BK;               // 8

    auto load_tile = [&](int it) {
        const int k0 = it * BK;
        const uint32_t sa = sbase + (uint32_t)(it & 1) * GSTG_BYTES;
        const uint32_t sb = sa + BM * SROW;
#pragma unroll
        for (int t = tid; t < 1024; t += THREADS) {     // A: 128 x 8 chunks
            int r = t >> 3, c = t & 7;
            cp16(sa + r * SROW + c * 16, A + (size_t)(bm + r) * 512 + k0 + c * 8);
        }
#pragma unroll
        for (int t = tid; t < 768; t += THREADS) {      // B: 96 x 8 chunks
            int r = t >> 3, c = t & 7;
            cp16(sb + r * SROW + c * 16, Bw + (size_t)r * 512 + k0 + c * 8);
        }
        cp_commit();
    };

    load_tile(0);

    for (int it = 0; it < niter; it++) {
        if (it + 1 < niter) {
            load_tile(it + 1);
            cp_wait<1>();
        } else {
            cp_wait<0>();
        }
        __syncthreads();

        const uint32_t sa = sbase + (uint32_t)(it & 1) * GSTG_BYTES;
        const uint32_t sb = sa + BM * SROW;

#pragma unroll
        for (int kk = 0; kk < BK; kk += 16) {
            uint32_t af[2][4], bf[6][2];
#pragma unroll
            for (int mt = 0; mt < 2; mt++)
                ldsm4(af[mt], sa + (wm + mt * 16 + arow) * SROW + (kk + acol) * 2);
#pragma unroll
            for (int np = 0; np < 3; np++) {
                uint32_t r[4];
                ldsm4(r, sb + (wn + np * 16 + brow) * SROW + (kk + bcol) * 2);
                bf[2 * np][0] = r[0]; bf[2 * np][1] = r[1];
                bf[2 * np + 1][0] = r[2]; bf[2 * np + 1][1] = r[3];
            }
#pragma unroll
            for (int mt = 0; mt < 2; mt++)
#pragma unroll
                for (int nt = 0; nt < 6; nt++)
                    mma16(acc[mt][nt], af[mt], bf[nt]);
        }
        __syncthreads();
    }

    // ---- register-local GRU gate epilogue ----
    // latent dims of this thread: c, c+1
    const int c = blk * 16 + (wn / 48) * 8 + qid * 2;
    const float2 bir = *(const float2*)(b_ih + c);
    const float2 biz = *(const float2*)(b_ih + 512 + c);
    const float2 bin = *(const float2*)(b_ih + 1024 + c);
    const float2 bhr = *(const float2*)(b_hh + c);
    const float2 bhz = *(const float2*)(b_hh + 512 + c);
    const float2 bhn = *(const float2*)(b_hh + 1024 + c);

#pragma unroll
    for (int mt = 0; mt < 2; mt++) {
#pragma unroll
        for (int hv = 0; hv < 2; hv++) {     // hv=0: row grp (k 0,1); hv=1: +8 (k 2,3)
            const int row = bm + wm + mt * 16 + grp + hv * 8;
            const int k0 = hv * 2;
            const float2 hin = *(const float2*)(latf_in + (size_t)row * 512 + c);

            float r0 = sigmf(acc[mt][0][k0]     + bir.x + acc[mt][3][k0]     + bhr.x);
            float r1 = sigmf(acc[mt][0][k0 + 1] + bir.y + acc[mt][3][k0 + 1] + bhr.y);
            float z0 = sigmf(acc[mt][1][k0]     + biz.x + acc[mt][4][k0]     + bhz.x);
            float z1 = sigmf(acc[mt][1][k0 + 1] + biz.y + acc[mt][4][k0 + 1] + bhz.y);
            float n0 = tanhf(acc[mt][2][k0]     + bin.x + r0 * (acc[mt][5][k0]     + bhn.x));
            float n1 = tanhf(acc[mt][2][k0 + 1] + bin.y + r1 * (acc[mt][5][k0 + 1] + bhn.y));
            float o0 = (1.f - z0) * n0 + z0 * hin.x;
            float o1 = (1.f - z1) * n1 + z1 * hin.y;

            *(float2*)(latf_out + (size_t)row * 512 + c) = make_float2(o0, o1);
            *(__half2*)(lath_out + (size_t)row * 512 + c) = __floats2half2_rn(o0, o1);
            *(float2*)(traj + (size_t)row * 4096 + step * 512 + c) = make_float2(o0, o1);
        }
    }
}

// ---------------- prep kernels -------------------------------------------------
__global__ __launch_bounds__(256) void f2h(const float4* __restrict__ in,
                                           __half2* __restrict__ out, int n4)
{
    int i = blockIdx.x * blockDim.x + threadIdx.x;
    if (i >= n4) return;
    float4 v = in[i];
    out[2 * i]     = __floats2half2_rn(v.x, v.y);
    out[2 * i + 1] = __floats2half2_rn(v.z, v.w);
}

// gate-grouped GRU weight reorder (8-dim groups):
// out row o: d48 = o/48, g = (o%48)/8, e = o%8; c = d48*8 + e;
// src = g<3 ? w_ih row (g*512+c) : w_hh row ((g-3)*512+c). 128 x float4 per row.
__global__ __launch_bounds__(256) void reorder_w(
    const float* __restrict__ w_ih, const float* __restrict__ w_hh,
    __half* __restrict__ wg)
{
    int idx = blockIdx.x * blockDim.x + threadIdx.x;   // 3072*128
    if (idx >= 3072 * 128) return;
    int o = idx >> 7, q = idx & 127;
    int d48 = o / 48, rem = o % 48, g = rem >> 3, e = rem & 7;
    int c = d48 * 8 + e;
    const float* src = (g < 3) ? (w_ih + (size_t)(g * 512 + c) * 512)
                               : (w_hh + (size_t)((g - 3) * 512 + c) * 512);
    float4 v = ((const float4*)src)[q];
    __half2* dst = (__half2*)(wg + (size_t)o * 512 + q * 4);
    dst[0] = __floats2half2_rn(v.x, v.y);
    dst[1] = __floats2half2_rn(v.z, v.w);
}

// ---------------- launch -------------------------------------------------------
extern "C" void kernel_launch(void* const* d_in, const int* in_sizes, int n_in,
                              void* d_out, int out_size)
{
    const int bse = (n_in >= 14) ? 2 : 1;
    const float* x      = (const float*)d_in[0];
    const float* W_enc1 = (const float*)d_in[bse + 0];
    const float* b_enc1 = (const float*)d_in[bse + 1];
    const float* W_enc2 = (const float*)d_in[bse + 2];
    const float* b_enc2 = (const float*)d_in[bse + 3];
    const float* W_dec1 = (const float*)d_in[bse + 4];
    const float* b_dec1 = (const float*)d_in[bse + 5];
    const float* W_dec2 = (const float*)d_in[bse + 6];
    const float* b_dec2 = (const float*)d_in[bse + 7];
    const float* w_ih   = (const float*)d_in[bse + 8];
    const float* w_hh   = (const float*)d_in[bse + 9];
    const float* b_ih   = (const float*)d_in[bse + 10];
    const float* b_hh   = (const float*)d_in[bse + 11];

    float* decoded = (float*)d_out;
    float* traj    = decoded + (size_t)MROWS * 2048;

    __half *xh, *h1h, *wh, *wg;
    __half *lath[2];
    float *latf[2];
    cudaGetSymbolAddress((void**)&xh,  g_xh);
    cudaGetSymbolAddress((void**)&h1h, g_h1h);
    cudaGetSymbolAddress((void**)&wh,  g_wh);
    cudaGetSymbolAddress((void**)&wg,  g_wgru);
    {   __half* p; cudaGetSymbolAddress((void**)&p, g_lath);
        lath[0] = p; lath[1] = p + (size_t)MROWS * 512; }
    {   float* p; cudaGetSymbolAddress((void**)&p, g_latf);
        latf[0] = p; latf[1] = p + (size_t)MROWS * 512; }

    cudaFuncSetAttribute(gemm_f16, cudaFuncAttributeMaxDynamicSharedMemorySize, SMEM_MAIN);
    cudaFuncSetAttribute(gemm_gru, cudaFuncAttributeMaxDynamicSharedMemorySize, SMEM_GRU);

    auto cvt = [&](const float* src, __half* dst, int n) {
        f2h<<<(n / 4 + 255) / 256, 256>>>((const float4*)src, (__half2*)dst, n / 4);
    };
    cvt(x,      xh,            MROWS * 2048);
    cvt(W_enc1, wh + OFF_ENC1, 1024 * 2048);
    cvt(W_enc2, wh + OFF_ENC2, 512 * 1024);
    cvt(W_dec1, wh + OFF_DEC1, 1024 * 512);
    cvt(W_dec2, wh + OFF_DEC2, 2048 * 1024);
    reorder_w<<<(3072 * 128 + 255) / 256, 256>>>(w_ih, w_hh, wg);

    const dim3 blk(THREADS);
    const int gy = MROWS / BM;  // 64

    // encode
    gemm_f16<<<dim3(1024 / BN, gy), blk, SMEM_MAIN>>>(
        xh, 2048, wh + OFF_ENC1, 2048, b_enc1, nullptr, h1h, 1024, 2048, 1);
    gemm_f16<<<dim3(512 / BN, gy), blk, SMEM_MAIN>>>(
        h1h, 1024, wh + OFF_ENC2, 1024, b_enc2, latf[0], lath[0], 512, 1024, 0);

    // 8 fused GRU steps (ping-pong latent buffers)
    for (int step = 0; step < 8; step++) {
        int s = step & 1, t = s ^ 1;
        gemm_gru<<<dim3(32, MROWS / BM), blk, SMEM_GRU>>>(
            lath[s], b_ih, b_hh, latf[s], latf[t], lath[t], traj, step);
    }

    // decode (after 8 steps latent is back in buffer 0)
    gemm_f16<<<dim3(1024 / BN, gy), blk, SMEM_MAIN>>>(
        lath[0], 512, wh + OFF_DEC1, 512, b_dec1, nullptr, h1h, 1024, 512, 1);
    gemm_f16<<<dim3(2048 / BN, gy), blk, SMEM_MAIN>>>(
        h1h, 1024, wh + OFF_DEC2, 1024, b_dec2, decoded, nullptr, 2048, 1024, 0);
}

// round 6
// speedup vs baseline: 1.4096x; 1.1195x over previous
#include <cuda_runtime.h>
#include <cuda_fp16.h>
#include <cstdint>

// ----------------------------------------------------------------------------
// LatentReasoningModule, sm_100 legacy tensor-core path.
//   fp16 mma.m16n8k16 (fp32 accum), ldmatrix, 3-stage cp.async, 1 sync/k-tile.
//   encode: H(2048)->2L(1024) relu ->L(512)
//   8x GRU(512): fused GEMM+gate kernel (8-dim gate-grouped weights,
//                register-local gate math).
//   decode: L->2L relu ->H
//   Single mega-prep kernel (all fp32->fp16 + GRU weight reorder).
// ----------------------------------------------------------------------------

#define MROWS 8192
#define THREADS 256
#define SROW 144                    // bytes per smem row: 64 halves + 8 pad

// ---- main GEMM tile (encode/decode): 3-stage ----
#define BM 128
#define BN 128
#define BK 64
#define AB_BYTES   (BM * SROW)          // 18432
#define STG_BYTES  (2 * AB_BYTES)       // 36864
#define SMEM_MAIN  (3 * STG_BYTES)      // 110592

// ---- GRU GEMM tile: BM=128, BN=96, 3-stage ----
#define GBN 96
#define GSTG_BYTES ((BM + GBN) * SROW)  // 32256
#define SMEM_GRU   (3 * GSTG_BYTES)     // 96768

// ---------------- scratch (device globals) ------------------------------------
__device__ __half g_xh[(size_t)MROWS * 2048];
__device__ __half g_h1h[(size_t)MROWS * 1024];
__device__ __half g_lath[2][(size_t)MROWS * 512];
__device__ float  g_latf[2][(size_t)MROWS * 512];
#define OFF_ENC1  0
#define OFF_ENC2  2097152
#define OFF_DEC1  2621440
#define OFF_DEC2  3145728
__device__ __half g_wh[5242880];
__device__ __half g_wgru[3072 * 512];   // gate-grouped GRU weights (8-dim groups)

// ---------------- helpers -----------------------------------------------------
__device__ __forceinline__ uint32_t smem_u32(const void* p) {
    uint32_t a;
    asm("{ .reg .u64 t; cvta.to.shared.u64 t, %1; cvt.u32.u64 %0, t; }"
        : "=r"(a) : "l"(p));
    return a;
}
__device__ __forceinline__ void cp16(uint32_t dst, const void* src) {
    asm volatile("cp.async.cg.shared.global [%0], [%1], 16;"
                 :: "r"(dst), "l"(src));
}
__device__ __forceinline__ void cp_commit() {
    asm volatile("cp.async.commit_group;" ::: "memory");
}
template <int N>
__device__ __forceinline__ void cp_wait() {
    asm volatile("cp.async.wait_group %0;" :: "n"(N) : "memory");
}
__device__ __forceinline__ void ldsm4(uint32_t* r, uint32_t addr) {
    asm volatile("ldmatrix.sync.aligned.m8n8.x4.shared.b16 {%0,%1,%2,%3}, [%4];"
                 : "=r"(r[0]), "=r"(r[1]), "=r"(r[2]), "=r"(r[3]) : "r"(addr));
}
__device__ __forceinline__ void mma16(float* c, const uint32_t* a, const uint32_t* b) {
    asm volatile(
        "mma.sync.aligned.m16n8k16.row.col.f32.f16.f16.f32 "
        "{%0,%1,%2,%3},{%4,%5,%6,%7},{%8,%9},{%0,%1,%2,%3};"
        : "+f"(c[0]), "+f"(c[1]), "+f"(c[2]), "+f"(c[3])
        : "r"(a[0]), "r"(a[1]), "r"(a[2]), "r"(a[3]), "r"(b[0]), "r"(b[1]));
}
__device__ __forceinline__ float sigmf(float x) {
    return 1.f / (1.f + __expf(-x));
}

// ---------------- main fp16 GEMM (encode/decode) -------------------------------
__global__ __launch_bounds__(THREADS, 2) void gemm_f16(
    const __half* __restrict__ A, int lda,
    const __half* __restrict__ B, int ldb,
    const float* __restrict__ bias,
    float* __restrict__ Cf, __half* __restrict__ Ch, int ldc,
    int K, int do_relu)
{
    extern __shared__ __align__(16) char sm[];
    const uint32_t sbase = smem_u32(sm);

    const int tid  = threadIdx.x;
    const int warp = tid >> 5;
    const int lane = tid & 31;
    const int bm = blockIdx.y * BM;
    const int bn = blockIdx.x * BN;
    const int wm = (warp & 3) * 32;
    const int wn = (warp >> 2) * 64;
    const int grp = lane >> 2;
    const int qid = lane & 3;
    const int arow = ((lane >> 3) & 1) * 8 + (lane & 7);
    const int acol = ((lane >> 4) & 1) * 8;
    const int brow = ((lane >> 4) & 1) * 8 + (lane & 7);
    const int bcol = ((lane >> 3) & 1) * 8;

    float acc[2][8][4];
#pragma unroll
    for (int i = 0; i < 2; i++)
#pragma unroll
        for (int j = 0; j < 8; j++)
#pragma unroll
            for (int k = 0; k < 4; k++) acc[i][j][k] = 0.f;

    const int niter = K / BK;

    auto load_tile = [&](int it) {
        const int k0 = it * BK;
        const uint32_t sa = sbase + (uint32_t)(it % 3) * STG_BYTES;
        const uint32_t sb = sa + AB_BYTES;
#pragma unroll
        for (int t = tid; t < 1024; t += THREADS) {
            int r = t >> 3, c = t & 7;
            cp16(sa + r * SROW + c * 16, A + (size_t)(bm + r) * lda + k0 + c * 8);
        }
#pragma unroll
        for (int t = tid; t < 1024; t += THREADS) {
            int r = t >> 3, c = t & 7;
            cp16(sb + r * SROW + c * 16, B + (size_t)(bn + r) * ldb + k0 + c * 8);
        }
        cp_commit();
    };

    load_tile(0);
    load_tile(1);

    for (int it = 0; it < niter; it++) {
        if (it + 1 < niter) cp_wait<1>(); else cp_wait<0>();
        __syncthreads();                    // single barrier per k-tile
        if (it + 2 < niter) load_tile(it + 2);

        const uint32_t sa = sbase + (uint32_t)(it % 3) * STG_BYTES;
        const uint32_t sb = sa + AB_BYTES;

#pragma unroll
        for (int kk = 0; kk < BK; kk += 16) {
            uint32_t af[2][4], bf[8][2];
#pragma unroll
            for (int mt = 0; mt < 2; mt++)
                ldsm4(af[mt], sa + (wm + mt * 16 + arow) * SROW + (kk + acol) * 2);
#pragma unroll
            for (int np = 0; np < 4; np++) {
                uint32_t r[4];
                ldsm4(r, sb + (wn + np * 16 + brow) * SROW + (kk + bcol) * 2);
                bf[2 * np][0] = r[0]; bf[2 * np][1] = r[1];
                bf[2 * np + 1][0] = r[2]; bf[2 * np + 1][1] = r[3];
            }
#pragma unroll
            for (int mt = 0; mt < 2; mt++)
#pragma unroll
                for (int nt = 0; nt < 8; nt++)
                    mma16(acc[mt][nt], af[mt], bf[nt]);
        }
    }

#pragma unroll
    for (int mt = 0; mt < 2; mt++) {
#pragma unroll
        for (int nt = 0; nt < 8; nt++) {
            int colN = bn + wn + nt * 8 + qid * 2;
            int row  = bm + wm + mt * 16 + grp;
            float2 bv = *(const float2*)(bias + colN);
            float2 v0, v1;
            v0.x = acc[mt][nt][0] + bv.x; v0.y = acc[mt][nt][1] + bv.y;
            v1.x = acc[mt][nt][2] + bv.x; v1.y = acc[mt][nt][3] + bv.y;
            if (do_relu) {
                v0.x = fmaxf(v0.x, 0.f); v0.y = fmaxf(v0.y, 0.f);
                v1.x = fmaxf(v1.x, 0.f); v1.y = fmaxf(v1.y, 0.f);
            }
            if (Cf) {
                *(float2*)(Cf + (size_t)row * ldc + colN)       = v0;
                *(float2*)(Cf + (size_t)(row + 8) * ldc + colN) = v1;
            }
            if (Ch) {
                *(__half2*)(Ch + (size_t)row * ldc + colN)       = __floats2half2_rn(v0.x, v0.y);
                *(__half2*)(Ch + (size_t)(row + 8) * ldc + colN) = __floats2half2_rn(v1.x, v1.y);
            }
        }
    }
}

// ---------------- fused GRU step ------------------------------------------------
// CTA tile 128x96 (2 x 48-col gate groups = 16 latent dims x 6 gates).
// Warp tile 32x48; each thread owns all 6 gate pre-acts for dims qid*2, qid*2+1.
__global__ __launch_bounds__(THREADS, 2) void gemm_gru(
    const __half* __restrict__ A,
    const float* __restrict__ b_ih, const float* __restrict__ b_hh,
    const float* __restrict__ latf_in,
    float* __restrict__ latf_out, __half* __restrict__ lath_out,
    float* __restrict__ traj, int step)
{
    extern __shared__ __align__(16) char sm[];
    const uint32_t sbase = smem_u32(sm);

    const int tid  = threadIdx.x;
    const int warp = tid >> 5;
    const int lane = tid & 31;
    const int bm  = blockIdx.y * BM;
    const int blk = blockIdx.x;               // 16-dim block, 0..31
    const int wm = (warp & 3) * 32;
    const int wn = (warp >> 2) * 48;          // 0 or 48
    const int grp = lane >> 2;
    const int qid = lane & 3;
    const int arow = ((lane >> 3) & 1) * 8 + (lane & 7);
    const int acol = ((lane >> 4) & 1) * 8;
    const int brow = ((lane >> 4) & 1) * 8 + (lane & 7);
    const int bcol = ((lane >> 3) & 1) * 8;

    const __half* Bw = g_wgru + (size_t)blk * GBN * 512;

    float acc[2][6][4];
#pragma unroll
    for (int i = 0; i < 2; i++)
#pragma unroll
        for (int j = 0; j < 6; j++)
#pragma unroll
            for (int k = 0; k < 4; k++) acc[i][j][k] = 0.f;

    const int niter = 512 / BK;               // 8

    auto load_tile = [&](int it) {
        const int k0 = it * BK;
        const uint32_t sa = sbase + (uint32_t)(it % 3) * GSTG_BYTES;
        const uint32_t sb = sa + BM * SROW;
#pragma unroll
        for (int t = tid; t < 1024; t += THREADS) {     // A: 128 x 8 chunks
            int r = t >> 3, c = t & 7;
            cp16(sa + r * SROW + c * 16, A + (size_t)(bm + r) * 512 + k0 + c * 8);
        }
#pragma unroll
        for (int t = tid; t < 768; t += THREADS) {      // B: 96 x 8 chunks
            int r = t >> 3, c = t & 7;
            cp16(sb + r * SROW + c * 16, Bw + (size_t)r * 512 + k0 + c * 8);
        }
        cp_commit();
    };

    load_tile(0);
    load_tile(1);

    for (int it = 0; it < niter; it++) {
        if (it + 1 < niter) cp_wait<1>(); else cp_wait<0>();
        __syncthreads();
        if (it + 2 < niter) load_tile(it + 2);

        const uint32_t sa = sbase + (uint32_t)(it % 3) * GSTG_BYTES;
        const uint32_t sb = sa + BM * SROW;

#pragma unroll
        for (int kk = 0; kk < BK; kk += 16) {
            uint32_t af[2][4], bf[6][2];
#pragma unroll
            for (int mt = 0; mt < 2; mt++)
                ldsm4(af[mt], sa + (wm + mt * 16 + arow) * SROW + (kk + acol) * 2);
#pragma unroll
            for (int np = 0; np < 3; np++) {
                uint32_t r[4];
                ldsm4(r, sb + (wn + np * 16 + brow) * SROW + (kk + bcol) * 2);
                bf[2 * np][0] = r[0]; bf[2 * np][1] = r[1];
                bf[2 * np + 1][0] = r[2]; bf[2 * np + 1][1] = r[3];
            }
#pragma unroll
            for (int mt = 0; mt < 2; mt++)
#pragma unroll
                for (int nt = 0; nt < 6; nt++)
                    mma16(acc[mt][nt], af[mt], bf[nt]);
        }
    }

    // ---- register-local GRU gate epilogue ----
    const int c = blk * 16 + (wn / 48) * 8 + qid * 2;
    const float2 bir = *(const float2*)(b_ih + c);
    const float2 biz = *(const float2*)(b_ih + 512 + c);
    const float2 bin = *(const float2*)(b_ih + 1024 + c);
    const float2 bhr = *(const float2*)(b_hh + c);
    const float2 bhz = *(const float2*)(b_hh + 512 + c);
    const float2 bhn = *(const float2*)(b_hh + 1024 + c);

#pragma unroll
    for (int mt = 0; mt < 2; mt++) {
#pragma unroll
        for (int hv = 0; hv < 2; hv++) {
            const int row = bm + wm + mt * 16 + grp + hv * 8;
            const int k0 = hv * 2;
            const float2 hin = *(const float2*)(latf_in + (size_t)row * 512 + c);

            float r0 = sigmf(acc[mt][0][k0]     + bir.x + acc[mt][3][k0]     + bhr.x);
            float r1 = sigmf(acc[mt][0][k0 + 1] + bir.y + acc[mt][3][k0 + 1] + bhr.y);
            float z0 = sigmf(acc[mt][1][k0]     + biz.x + acc[mt][4][k0]     + bhz.x);
            float z1 = sigmf(acc[mt][1][k0 + 1] + biz.y + acc[mt][4][k0 + 1] + bhz.y);
            float n0 = tanhf(acc[mt][2][k0]     + bin.x + r0 * (acc[mt][5][k0]     + bhn.x));
            float n1 = tanhf(acc[mt][2][k0 + 1] + bin.y + r1 * (acc[mt][5][k0 + 1] + bhn.y));
            float o0 = (1.f - z0) * n0 + z0 * hin.x;
            float o1 = (1.f - z1) * n1 + z1 * hin.y;

            *(float2*)(latf_out + (size_t)row * 512 + c) = make_float2(o0, o1);
            *(__half2*)(lath_out + (size_t)row * 512 + c) = __floats2half2_rn(o0, o1);
            *(float2*)(traj + (size_t)row * 4096 + step * 512 + c) = make_float2(o0, o1);
        }
    }
}

// ---------------- mega prep kernel (single launch) ------------------------------
// Converts x + 4 enc/dec weights to fp16 and builds gate-grouped GRU weights.
#define PQ_X    4194304                 // 8192*2048/4
#define PQ_E1   (PQ_X + 524288)         // +1024*2048/4
#define PQ_E2   (PQ_E1 + 131072)        // +512*1024/4
#define PQ_D1   (PQ_E2 + 131072)        // +1024*512/4
#define PQ_D2   (PQ_D1 + 524288)        // +2048*1024/4
#define PQ_GRU  (PQ_D2 + 393216)        // +3072*128
__global__ __launch_bounds__(256) void prep(
    const float* __restrict__ x,
    const float* __restrict__ We1, const float* __restrict__ We2,
    const float* __restrict__ Wd1, const float* __restrict__ Wd2,
    const float* __restrict__ w_ih, const float* __restrict__ w_hh)
{
    int i = blockIdx.x * blockDim.x + threadIdx.x;
    if (i >= PQ_GRU) return;
    const float4* src;
    __half2* dst;
    if (i < PQ_X) {
        src = (const float4*)x + i;
        dst = (__half2*)g_xh + 2 * (size_t)i;
    } else if (i < PQ_E1) {
        int j = i - PQ_X;
        src = (const float4*)We1 + j;
        dst = (__half2*)(g_wh + OFF_ENC1) + 2 * (size_t)j;
    } else if (i < PQ_E2) {
        int j = i - PQ_E1;
        src = (const float4*)We2 + j;
        dst = (__half2*)(g_wh + OFF_ENC2) + 2 * (size_t)j;
    } else if (i < PQ_D1) {
        int j = i - PQ_E2;
        src = (const float4*)Wd1 + j;
        dst = (__half2*)(g_wh + OFF_DEC1) + 2 * (size_t)j;
    } else if (i < PQ_D2) {
        int j = i - PQ_D1;
        src = (const float4*)Wd2 + j;
        dst = (__half2*)(g_wh + OFF_DEC2) + 2 * (size_t)j;
    } else {
        int j = i - PQ_D2;                 // gru reorder: 3072 rows x 128 quads
        int o = j >> 7, q = j & 127;
        int d48 = o / 48, rem = o % 48, g = rem >> 3, e = rem & 7;
        int cc = d48 * 8 + e;
        const float* s = (g < 3) ? (w_ih + (size_t)(g * 512 + cc) * 512)
                                 : (w_hh + (size_t)((g - 3) * 512 + cc) * 512);
        src = (const float4*)s + q;
        dst = (__half2*)(g_wgru + (size_t)o * 512) + 2 * q;
    }
    float4 v = *src;
    dst[0] = __floats2half2_rn(v.x, v.y);
    dst[1] = __floats2half2_rn(v.z, v.w);
}

// ---------------- launch ---------------------------------------------------------
extern "C" void kernel_launch(void* const* d_in, const int* in_sizes, int n_in,
                              void* d_out, int out_size)
{
    const int bse = (n_in >= 14) ? 2 : 1;
    const float* x      = (const float*)d_in[0];
    const float* W_enc1 = (const float*)d_in[bse + 0];
    const float* b_enc1 = (const float*)d_in[bse + 1];
    const float* W_enc2 = (const float*)d_in[bse + 2];
    const float* b_enc2 = (const float*)d_in[bse + 3];
    const float* W_dec1 = (const float*)d_in[bse + 4];
    const float* b_dec1 = (const float*)d_in[bse + 5];
    const float* W_dec2 = (const float*)d_in[bse + 6];
    const float* b_dec2 = (const float*)d_in[bse + 7];
    const float* w_ih   = (const float*)d_in[bse + 8];
    const float* w_hh   = (const float*)d_in[bse + 9];
    const float* b_ih   = (const float*)d_in[bse + 10];
    const float* b_hh   = (const float*)d_in[bse + 11];

    float* decoded = (float*)d_out;
    float* traj    = decoded + (size_t)MROWS * 2048;

    __half *xh, *h1h, *wh;
    __half *lath[2];
    float *latf[2];
    cudaGetSymbolAddress((void**)&xh,  g_xh);
    cudaGetSymbolAddress((void**)&h1h, g_h1h);
    cudaGetSymbolAddress((void**)&wh,  g_wh);
    {   __half* p; cudaGetSymbolAddress((void**)&p, g_lath);
        lath[0] = p; lath[1] = p + (size_t)MROWS * 512; }
    {   float* p; cudaGetSymbolAddress((void**)&p, g_latf);
        latf[0] = p; latf[1] = p + (size_t)MROWS * 512; }

    cudaFuncSetAttribute(gemm_f16, cudaFuncAttributeMaxDynamicSharedMemorySize, SMEM_MAIN);
    cudaFuncSetAttribute(gemm_gru, cudaFuncAttributeMaxDynamicSharedMemorySize, SMEM_GRU);

    const dim3 blk(THREADS);
    const int gy = MROWS / BM;  // 64

    // launch 0: all prep work in one kernel
    prep<<<(PQ_GRU + 255) / 256, 256>>>(x, W_enc1, W_enc2, W_dec1, W_dec2,
                                        w_ih, w_hh);

    // launches 1,2: encode
    gemm_f16<<<dim3(1024 / BN, gy), blk, SMEM_MAIN>>>(
        xh, 2048, wh + OFF_ENC1, 2048, b_enc1, nullptr, h1h, 1024, 2048, 1);
    gemm_f16<<<dim3(512 / BN, gy), blk, SMEM_MAIN>>>(
        h1h, 1024, wh + OFF_ENC2, 1024, b_enc2, latf[0], lath[0], 512, 1024, 0);

    // launches 3..10: 8 fused GRU steps (launch #5 = step 2, for ncu -s 5)
    for (int step = 0; step < 8; step++) {
        int s = step & 1, t = s ^ 1;
        gemm_gru<<<dim3(32, MROWS / BM), blk, SMEM_GRU>>>(
            lath[s], b_ih, b_hh, latf[s], latf[t], lath[t], traj, step);
    }

    // launches 11,12: decode
    gemm_f16<<<dim3(1024 / BN, gy), blk, SMEM_MAIN>>>(
        lath[0], 512, wh + OFF_DEC1, 512, b_dec1, nullptr, h1h, 1024, 512, 1);
    gemm_f16<<<dim3(2048 / BN, gy), blk, SMEM_MAIN>>>(
        h1h, 1024, wh + OFF_DEC2, 1024, b_dec2, decoded, nullptr, 2048, 1024, 0);
}